// round 1
// baseline (speedup 1.0000x reference)
#include <cuda_runtime.h>
#include <cstdint>
#include <math.h>

// Problem constants
static constexpr int B_ = 8;
static constexpr int S_ = 2048;
static constexpr int D_ = 1024;
static constexpr int H_ = 1024;

// Device scratch (allocation-free rule: __device__ globals)
__device__ float g_q[(size_t)B_ * S_ * H_];
__device__ float g_k[(size_t)B_ * S_ * H_];
__device__ float g_v[(size_t)B_ * S_ * H_];
__device__ float g_p[(size_t)B_ * S_ * S_];

// ---------------------------------------------------------------------------
// 3xTF32 helpers
// ---------------------------------------------------------------------------
__device__ __forceinline__ void split_tf32(float x, uint32_t& h, uint32_t& l) {
    uint32_t xh;
    asm("cvt.rna.tf32.f32 %0, %1;" : "=r"(xh) : "f"(x));
    float r = x - __uint_as_float(xh);
    uint32_t xl;
    asm("cvt.rna.tf32.f32 %0, %1;" : "=r"(xl) : "f"(r));
    h = xh; l = xl;
}

__device__ __forceinline__ void mma8(float* d, const uint32_t* a, const uint32_t* b) {
    asm volatile(
        "mma.sync.aligned.m16n8k8.row.col.f32.tf32.tf32.f32 "
        "{%0,%1,%2,%3},{%4,%5,%6,%7},{%8,%9},{%0,%1,%2,%3};"
        : "+f"(d[0]), "+f"(d[1]), "+f"(d[2]), "+f"(d[3])
        : "r"(a[0]), "r"(a[1]), "r"(a[2]), "r"(a[3]), "r"(b[0]), "r"(b[1]));
}

// ---------------------------------------------------------------------------
// NT GEMM: C[m,n] = sum_k A[m,k] * B[n,k]   (both row-major, contract last dim)
// MODE 0: epilogue adds bias[n]               (QKV projection)
// MODE 1: epilogue scales + causal mask -1e9  (attention scores)
// Tile: BM=128, BN=64, BK=16, 256 threads (8 warps, 4x2, warp tile 32x32)
// ---------------------------------------------------------------------------
template <int MODE>
__global__ __launch_bounds__(256) void gemm_nt(
    const float* __restrict__ A, const float* __restrict__ Bm,
    const float* __restrict__ bias, float* __restrict__ C,
    int K, int lda, int ldb, int ldc,
    long sAz, long sBz, long sCz, float scale)
{
    constexpr int BM = 128, BN = 64, BK = 16, AST = 20, BST = 20;
    const int m0 = blockIdx.y * BM;
    const int n0 = blockIdx.x * BN;
    if (MODE == 1 && n0 >= m0 + BM) return;  // fully-masked tile

    const int z = blockIdx.z;
    A  += (size_t)z * sAz;
    Bm += (size_t)z * sBz;
    C  += (size_t)z * sCz;

    __shared__ float AsH[BM][AST], AsL[BM][AST];
    __shared__ float BsH[BN][BST], BsL[BN][BST];

    const int tid  = threadIdx.x;
    const int lane = tid & 31;
    const int wid  = tid >> 5;
    const int wm   = wid >> 1;   // 0..3
    const int wn   = wid & 1;    // 0..1
    const int g    = lane >> 2;  // 0..7
    const int tg   = lane & 3;   // 0..3

    float acc[2][4][4];
#pragma unroll
    for (int i = 0; i < 2; i++)
#pragma unroll
        for (int j = 0; j < 4; j++)
#pragma unroll
            for (int t = 0; t < 4; t++) acc[i][j][t] = 0.f;

    const int KT = K / BK;
    for (int kt = 0; kt < KT; kt++) {
        const int k0 = kt * BK;
        float4 aR[2], bR;
#pragma unroll
        for (int i = 0; i < 2; i++) {
            int f4 = tid + i * 256;
            int r = f4 >> 2, cv = f4 & 3;
            aR[i] = *reinterpret_cast<const float4*>(A + (size_t)(m0 + r) * lda + k0 + cv * 4);
        }
        {
            int r = tid >> 2, cv = tid & 3;
            bR = *reinterpret_cast<const float4*>(Bm + (size_t)(n0 + r) * ldb + k0 + cv * 4);
        }
        __syncthreads();  // previous compute done reading SMEM
#pragma unroll
        for (int i = 0; i < 2; i++) {
            int f4 = tid + i * 256;
            int r = f4 >> 2, cv = f4 & 3;
            const float* pv = reinterpret_cast<const float*>(&aR[i]);
#pragma unroll
            for (int j = 0; j < 4; j++) {
                uint32_t h, l;
                split_tf32(pv[j], h, l);
                AsH[r][cv * 4 + j] = __uint_as_float(h);
                AsL[r][cv * 4 + j] = __uint_as_float(l);
            }
        }
        {
            int r = tid >> 2, cv = tid & 3;
            const float* pv = reinterpret_cast<const float*>(&bR);
#pragma unroll
            for (int j = 0; j < 4; j++) {
                uint32_t h, l;
                split_tf32(pv[j], h, l);
                BsH[r][cv * 4 + j] = __uint_as_float(h);
                BsL[r][cv * 4 + j] = __uint_as_float(l);
            }
        }
        __syncthreads();  // SMEM tile ready

#pragma unroll
        for (int ks = 0; ks < 2; ks++) {
            const int kk = ks * 8;
            uint32_t ah[2][4], al[2][4], bh[4][2], bl[4][2];
#pragma unroll
            for (int mt = 0; mt < 2; mt++) {
                int r0 = wm * 32 + mt * 16;
                ah[mt][0] = __float_as_uint(AsH[r0 + g][kk + tg]);
                ah[mt][1] = __float_as_uint(AsH[r0 + g + 8][kk + tg]);
                ah[mt][2] = __float_as_uint(AsH[r0 + g][kk + tg + 4]);
                ah[mt][3] = __float_as_uint(AsH[r0 + g + 8][kk + tg + 4]);
                al[mt][0] = __float_as_uint(AsL[r0 + g][kk + tg]);
                al[mt][1] = __float_as_uint(AsL[r0 + g + 8][kk + tg]);
                al[mt][2] = __float_as_uint(AsL[r0 + g][kk + tg + 4]);
                al[mt][3] = __float_as_uint(AsL[r0 + g + 8][kk + tg + 4]);
            }
#pragma unroll
            for (int nt = 0; nt < 4; nt++) {
                int c0 = wn * 32 + nt * 8;
                bh[nt][0] = __float_as_uint(BsH[c0 + g][kk + tg]);
                bh[nt][1] = __float_as_uint(BsH[c0 + g][kk + tg + 4]);
                bl[nt][0] = __float_as_uint(BsL[c0 + g][kk + tg]);
                bl[nt][1] = __float_as_uint(BsL[c0 + g][kk + tg + 4]);
            }
#pragma unroll
            for (int mt = 0; mt < 2; mt++)
#pragma unroll
                for (int nt = 0; nt < 4; nt++) {
                    mma8(acc[mt][nt], ah[mt], bh[nt]);  // hi*hi
                    mma8(acc[mt][nt], ah[mt], bl[nt]);  // hi*lo
                    mma8(acc[mt][nt], al[mt], bh[nt]);  // lo*hi
                }
        }
    }

    // Epilogue
#pragma unroll
    for (int mt = 0; mt < 2; mt++) {
#pragma unroll
        for (int nt = 0; nt < 4; nt++) {
            const int row = m0 + wm * 32 + mt * 16 + g;
            const int col = n0 + wn * 32 + nt * 8 + tg * 2;
            float* c = acc[mt][nt];
            if (MODE == 0) {
                const float b0 = bias[col], b1 = bias[col + 1];
                C[(size_t)row * ldc + col]           = c[0] + b0;
                C[(size_t)row * ldc + col + 1]       = c[1] + b1;
                C[(size_t)(row + 8) * ldc + col]     = c[2] + b0;
                C[(size_t)(row + 8) * ldc + col + 1] = c[3] + b1;
            } else {
                C[(size_t)row * ldc + col]           = (col     <= row    ) ? c[0] * scale : -1e9f;
                C[(size_t)row * ldc + col + 1]       = (col + 1 <= row    ) ? c[1] * scale : -1e9f;
                C[(size_t)(row + 8) * ldc + col]     = (col     <= row + 8) ? c[2] * scale : -1e9f;
                C[(size_t)(row + 8) * ldc + col + 1] = (col + 1 <= row + 8) ? c[3] * scale : -1e9f;
            }
        }
    }
}

// ---------------------------------------------------------------------------
// Row softmax on scores, in place. One block per row; reads only the causal
// prefix rounded up to 128 (matches scores tile coverage & PV k-limit).
// ---------------------------------------------------------------------------
__global__ __launch_bounds__(256) void softmax_rows(float* __restrict__ P) {
    const int r = blockIdx.x;          // 0 .. B*S-1
    const int m = r & (S_ - 1);
    float* row = P + (size_t)r * S_;
    const int KB = ((m >> 7) + 1) << 7;  // round_up(m+1, 128)

    __shared__ float buf[S_];
    __shared__ float red[8];
    const int tid = threadIdx.x;

    float mx = -3.4e38f;
    for (int i = tid; i < KB; i += 256) {
        float v = row[i];
        buf[i] = v;
        mx = fmaxf(mx, v);
    }
#pragma unroll
    for (int o = 16; o; o >>= 1) mx = fmaxf(mx, __shfl_xor_sync(0xffffffffu, mx, o));
    if ((tid & 31) == 0) red[tid >> 5] = mx;
    __syncthreads();
    if (tid == 0) {
        float t = red[0];
#pragma unroll
        for (int i = 1; i < 8; i++) t = fmaxf(t, red[i]);
        red[0] = t;
    }
    __syncthreads();
    mx = red[0];
    __syncthreads();

    float sm = 0.f;
    for (int i = tid; i < KB; i += 256) {
        float e = expf(buf[i] - mx);
        buf[i] = e;
        sm += e;
    }
#pragma unroll
    for (int o = 16; o; o >>= 1) sm += __shfl_xor_sync(0xffffffffu, sm, o);
    __syncthreads();
    if ((tid & 31) == 0) red[tid >> 5] = sm;
    __syncthreads();
    if (tid == 0) {
        float t = 0.f;
#pragma unroll
        for (int i = 0; i < 8; i++) t += red[i];
        red[0] = t;
    }
    __syncthreads();
    const float inv = 1.f / red[0];

    for (int i = tid; i < KB; i += 256) row[i] = buf[i] * inv;
}

// ---------------------------------------------------------------------------
// NN GEMM: C[m,n] = sum_k A[m,k] * B[k,n]  (PV product), causal k-limit m0+128
// ---------------------------------------------------------------------------
__global__ __launch_bounds__(256) void gemm_nn(
    const float* __restrict__ A, const float* __restrict__ Bm, float* __restrict__ C,
    int lda, int ldb, int ldc, long sAz, long sBz, long sCz)
{
    constexpr int BM = 128, BN = 64, BK = 16, AST = 20, BST = 72;
    const int m0 = blockIdx.y * BM;
    const int n0 = blockIdx.x * BN;
    const int z  = blockIdx.z;
    A  += (size_t)z * sAz;
    Bm += (size_t)z * sBz;
    C  += (size_t)z * sCz;

    __shared__ float AsH[BM][AST], AsL[BM][AST];
    __shared__ float BsH[BK][BST], BsL[BK][BST];

    const int tid  = threadIdx.x;
    const int lane = tid & 31;
    const int wid  = tid >> 5;
    const int wm   = wid >> 1;
    const int wn   = wid & 1;
    const int g    = lane >> 2;
    const int tg   = lane & 3;

    float acc[2][4][4];
#pragma unroll
    for (int i = 0; i < 2; i++)
#pragma unroll
        for (int j = 0; j < 4; j++)
#pragma unroll
            for (int t = 0; t < 4; t++) acc[i][j][t] = 0.f;

    const int Kend = m0 + BM;  // causal: P[m,k]==0 for k >= round_up(m+1,128)
    const int KT = Kend / BK;
    for (int kt = 0; kt < KT; kt++) {
        const int k0 = kt * BK;
        float4 aR[2], bR;
#pragma unroll
        for (int i = 0; i < 2; i++) {
            int f4 = tid + i * 256;
            int r = f4 >> 2, cv = f4 & 3;
            aR[i] = *reinterpret_cast<const float4*>(A + (size_t)(m0 + r) * lda + k0 + cv * 4);
        }
        {
            int r = tid >> 4, cv = tid & 15;  // 16 rows x 16 float4/row
            bR = *reinterpret_cast<const float4*>(Bm + (size_t)(k0 + r) * ldb + n0 + cv * 4);
        }
        __syncthreads();
#pragma unroll
        for (int i = 0; i < 2; i++) {
            int f4 = tid + i * 256;
            int r = f4 >> 2, cv = f4 & 3;
            const float* pv = reinterpret_cast<const float*>(&aR[i]);
#pragma unroll
            for (int j = 0; j < 4; j++) {
                uint32_t h, l;
                split_tf32(pv[j], h, l);
                AsH[r][cv * 4 + j] = __uint_as_float(h);
                AsL[r][cv * 4 + j] = __uint_as_float(l);
            }
        }
        {
            int r = tid >> 4, cv = tid & 15;
            const float* pv = reinterpret_cast<const float*>(&bR);
#pragma unroll
            for (int j = 0; j < 4; j++) {
                uint32_t h, l;
                split_tf32(pv[j], h, l);
                BsH[r][cv * 4 + j] = __uint_as_float(h);
                BsL[r][cv * 4 + j] = __uint_as_float(l);
            }
        }
        __syncthreads();

#pragma unroll
        for (int ks = 0; ks < 2; ks++) {
            const int kk = ks * 8;
            uint32_t ah[2][4], al[2][4], bh[4][2], bl[4][2];
#pragma unroll
            for (int mt = 0; mt < 2; mt++) {
                int r0 = wm * 32 + mt * 16;
                ah[mt][0] = __float_as_uint(AsH[r0 + g][kk + tg]);
                ah[mt][1] = __float_as_uint(AsH[r0 + g + 8][kk + tg]);
                ah[mt][2] = __float_as_uint(AsH[r0 + g][kk + tg + 4]);
                ah[mt][3] = __float_as_uint(AsH[r0 + g + 8][kk + tg + 4]);
                al[mt][0] = __float_as_uint(AsL[r0 + g][kk + tg]);
                al[mt][1] = __float_as_uint(AsL[r0 + g + 8][kk + tg]);
                al[mt][2] = __float_as_uint(AsL[r0 + g][kk + tg + 4]);
                al[mt][3] = __float_as_uint(AsL[r0 + g + 8][kk + tg + 4]);
            }
#pragma unroll
            for (int nt = 0; nt < 4; nt++) {
                int c0 = wn * 32 + nt * 8;
                bh[nt][0] = __float_as_uint(BsH[kk + tg][c0 + g]);
                bh[nt][1] = __float_as_uint(BsH[kk + tg + 4][c0 + g]);
                bl[nt][0] = __float_as_uint(BsL[kk + tg][c0 + g]);
                bl[nt][1] = __float_as_uint(BsL[kk + tg + 4][c0 + g]);
            }
#pragma unroll
            for (int mt = 0; mt < 2; mt++)
#pragma unroll
                for (int nt = 0; nt < 4; nt++) {
                    mma8(acc[mt][nt], ah[mt], bh[nt]);
                    mma8(acc[mt][nt], ah[mt], bl[nt]);
                    mma8(acc[mt][nt], al[mt], bh[nt]);
                }
        }
    }

#pragma unroll
    for (int mt = 0; mt < 2; mt++) {
#pragma unroll
        for (int nt = 0; nt < 4; nt++) {
            const int row = m0 + wm * 32 + mt * 16 + g;
            const int col = n0 + wn * 32 + nt * 8 + tg * 2;
            float* c = acc[mt][nt];
            C[(size_t)row * ldc + col]           = c[0];
            C[(size_t)row * ldc + col + 1]       = c[1];
            C[(size_t)(row + 8) * ldc + col]     = c[2];
            C[(size_t)(row + 8) * ldc + col + 1] = c[3];
        }
    }
}

// ---------------------------------------------------------------------------
// Launch pipeline (graph-capturable: kernel launches only, default stream)
// ---------------------------------------------------------------------------
extern "C" void kernel_launch(void* const* d_in, const int* in_sizes, int n_in,
                              void* d_out, int out_size)
{
    (void)in_sizes; (void)n_in; (void)out_size;
    const float* x  = (const float*)d_in[0];
    const float* Wq = (const float*)d_in[1];
    const float* bq = (const float*)d_in[2];
    const float* Wk = (const float*)d_in[3];
    const float* bk = (const float*)d_in[4];
    const float* Wv = (const float*)d_in[5];
    const float* bv = (const float*)d_in[6];
    float* out = (float*)d_out;

    float *q, *k, *v, *p;
    cudaGetSymbolAddress((void**)&q, g_q);
    cudaGetSymbolAddress((void**)&k, g_k);
    cudaGetSymbolAddress((void**)&v, g_v);
    cudaGetSymbolAddress((void**)&p, g_p);

    const dim3 blk(256);
    const int M = B_ * S_;  // 16384

    // 1) QKV projections: [16384,1024] = x[16384,1024] @ W^T + b
    const dim3 gqkv(H_ / 64, M / 128, 1);
    gemm_nt<0><<<gqkv, blk>>>(x, Wq, bq, q, D_, D_, D_, H_, 0, 0, 0, 1.f);
    gemm_nt<0><<<gqkv, blk>>>(x, Wk, bk, k, D_, D_, D_, H_, 0, 0, 0, 1.f);
    gemm_nt<0><<<gqkv, blk>>>(x, Wv, bv, v, D_, D_, D_, H_, 0, 0, 0, 1.f);

    // 2) Scores: per batch, S = Q @ K^T / sqrt(H), causal mask
    const dim3 gsc(S_ / 64, S_ / 128, B_);
    gemm_nt<1><<<gsc, blk>>>(q, k, nullptr, p, H_, H_, H_, S_,
                             (long)S_ * H_, (long)S_ * H_, (long)S_ * S_, 0.03125f);

    // 3) Row softmax (causal prefix only)
    softmax_rows<<<B_ * S_, blk>>>(p);

    // 4) O = P @ V, causal k-limit
    const dim3 gpv(H_ / 64, S_ / 128, B_);
    gemm_nn<<<gpv, blk>>>(p, v, out, S_, H_, H_,
                          (long)S_ * S_, (long)S_ * H_, (long)S_ * H_);
}

// round 2
// speedup vs baseline: 1.9572x; 1.9572x over previous
#include <cuda_runtime.h>
#include <cstdint>
#include <math.h>

static constexpr int B_ = 8, S_ = 2048, D_ = 1024, H_ = 1024;
static constexpr int BM = 128, BN = 128, BK = 16, SA = 20;
static constexpr int SMEM_FLOATS = 6 * BM * SA;          // 3 planes x 2 buffers
static constexpr int SMEM_BYTES = SMEM_FLOATS * 4;       // 61440

// Device scratch (allocation-free rule: __device__ globals)
__device__ float g_q[(size_t)B_ * S_ * H_];
__device__ float g_k[(size_t)B_ * S_ * H_];
__device__ float g_v[(size_t)B_ * S_ * H_];
__device__ float g_vt[(size_t)B_ * S_ * H_];
__device__ float g_p[(size_t)B_ * S_ * S_];

__device__ __forceinline__ float tf32_rna(float x) {
    uint32_t u;
    asm("cvt.rna.tf32.f32 %0, %1;" : "=r"(u) : "f"(x));
    return __uint_as_float(u);
}

__device__ __forceinline__ void mma8(float* d, const uint32_t* a, const uint32_t* b) {
    asm volatile(
        "mma.sync.aligned.m16n8k8.row.col.f32.tf32.tf32.f32 "
        "{%0,%1,%2,%3},{%4,%5,%6,%7},{%8,%9},{%0,%1,%2,%3};"
        : "+f"(d[0]), "+f"(d[1]), "+f"(d[2]), "+f"(d[3])
        : "r"(a[0]), "r"(a[1]), "r"(a[2]), "r"(a[3]), "r"(b[0]), "r"(b[1]));
}

// A plane: RNA-rounded tf32 hi only
__device__ __forceinline__ void store_A(float* dst, int lr, int lc, float4 v) {
    float4 c;
    c.x = tf32_rna(v.x); c.y = tf32_rna(v.y); c.z = tf32_rna(v.z); c.w = tf32_rna(v.w);
    *reinterpret_cast<float4*>(dst + lr * SA + lc) = c;
}
// B planes: hi + residual-lo split
__device__ __forceinline__ void store_B(float* dh, float* dl, int lr, int lc, float4 v) {
    float4 h, l;
    h.x = tf32_rna(v.x); l.x = tf32_rna(v.x - h.x);
    h.y = tf32_rna(v.y); l.y = tf32_rna(v.y - h.y);
    h.z = tf32_rna(v.z); l.z = tf32_rna(v.z - h.z);
    h.w = tf32_rna(v.w); l.w = tf32_rna(v.w - h.w);
    *reinterpret_cast<float4*>(dh + lr * SA + lc) = h;
    *reinterpret_cast<float4*>(dl + lr * SA + lc) = l;
}

__device__ __forceinline__ void compute_tile(
    const float* ah, const float* bh, const float* bl,
    float (&acc)[4][4][4], int aoff, int boff)
{
#pragma unroll
    for (int ks = 0; ks < BK; ks += 8) {
        uint32_t af[4][4], bf[4][2], bg[4][2];
#pragma unroll
        for (int mt = 0; mt < 4; mt++) {
            const float* p = ah + aoff + mt * 16 * SA + ks;
            af[mt][0] = __float_as_uint(p[0]);
            af[mt][1] = __float_as_uint(p[8 * SA]);
            af[mt][2] = __float_as_uint(p[4]);
            af[mt][3] = __float_as_uint(p[8 * SA + 4]);
        }
#pragma unroll
        for (int nt = 0; nt < 4; nt++) {
            const float* ph = bh + boff + nt * 8 * SA + ks;
            bf[nt][0] = __float_as_uint(ph[0]);
            bf[nt][1] = __float_as_uint(ph[4]);
            const float* pl = bl + boff + nt * 8 * SA + ks;
            bg[nt][0] = __float_as_uint(pl[0]);
            bg[nt][1] = __float_as_uint(pl[4]);
        }
#pragma unroll
        for (int mt = 0; mt < 4; mt++)
#pragma unroll
            for (int nt = 0; nt < 4; nt++) {
                mma8(acc[mt][nt], af[mt], bf[nt]);  // a_hi * b_hi
                mma8(acc[mt][nt], af[mt], bg[nt]);  // a_hi * b_lo
            }
    }
}

// ---------------------------------------------------------------------------
// NT GEMM: C[m,n] = sum_k A[m,k] * B[n,k], 2xTF32, double-buffered.
// MODE 0: + bias[n]           (QKV projections)
// MODE 2: scale + causal mask (scores; skips fully-masked tiles)
// MODE 3: plain, K = m0+BM    (PV with causal k-limit; B = V^T)
// ---------------------------------------------------------------------------
template <int MODE>
__global__ __launch_bounds__(256, 2) void gemm_nt(
    const float* __restrict__ A, const float* __restrict__ Bm,
    const float* __restrict__ bias, float* __restrict__ C,
    int K, int lda, int ldb, int ldc,
    long sAz, long sBz, long sCz, float scale)
{
    const int m0 = blockIdx.y * BM;
    const int n0 = blockIdx.x * BN;
    if (MODE == 2 && n0 > m0) return;  // fully masked tile

    const int z = blockIdx.z;
    A  += (size_t)z * sAz;
    Bm += (size_t)z * sBz;
    C  += (size_t)z * sCz;

    extern __shared__ float smem[];
    float* Ah = smem;
    float* Bh = smem + 2 * BM * SA;
    float* Bl = smem + 4 * BM * SA;

    const int tid  = threadIdx.x;
    const int lane = tid & 31;
    const int wid  = tid >> 5;
    const int wm   = wid >> 2;   // 0..1 (64 rows each)
    const int wn   = wid & 3;    // 0..3 (32 cols each)
    const int g    = lane >> 2;
    const int tg   = lane & 3;
    const int aoff = (wm * 64 + g) * SA + tg;
    const int boff = (wn * 32 + g) * SA + tg;

    const int Kend = (MODE == 3) ? (m0 + BM) : K;
    const int KT   = Kend / BK;

    const int lr = tid >> 2;
    const int lc = (tid & 3) * 4;
    const float* pA = A  + (size_t)(m0 + lr) * lda + lc;
    const float* pB = Bm + (size_t)(n0 + lr) * ldb + lc;
    const size_t a64 = (size_t)64 * lda, b64 = (size_t)64 * ldb;

    float acc[4][4][4];
#pragma unroll
    for (int i = 0; i < 4; i++)
#pragma unroll
        for (int j = 0; j < 4; j++)
#pragma unroll
            for (int e = 0; e < 4; e++) acc[i][j][e] = 0.f;

    // prologue: tile 0
    float4 ra0 = *(const float4*)pA;
    float4 ra1 = *(const float4*)(pA + a64);
    float4 rb0 = *(const float4*)pB;
    float4 rb1 = *(const float4*)(pB + b64);
    store_A(Ah, lr, lc, ra0);
    store_A(Ah, lr + 64, lc, ra1);
    store_B(Bh, Bl, lr, lc, rb0);
    store_B(Bh, Bl, lr + 64, lc, rb1);
    __syncthreads();

    for (int kt = 0; kt < KT; kt++) {
        const int cur = kt & 1;
        if (kt + 1 < KT) {  // prefetch next tile into registers
            const float* qA = pA + (kt + 1) * BK;
            const float* qB = pB + (kt + 1) * BK;
            ra0 = *(const float4*)qA;
            ra1 = *(const float4*)(qA + a64);
            rb0 = *(const float4*)qB;
            rb1 = *(const float4*)(qB + b64);
        }
        const int bo = cur * BM * SA;
        compute_tile(Ah + bo, Bh + bo, Bl + bo, acc, aoff, boff);
        if (kt + 1 < KT) {
            const int nb = (1 - cur) * BM * SA;
            store_A(Ah + nb, lr, lc, ra0);
            store_A(Ah + nb, lr + 64, lc, ra1);
            store_B(Bh + nb, Bl + nb, lr, lc, rb0);
            store_B(Bh + nb, Bl + nb, lr + 64, lc, rb1);
            __syncthreads();
        }
    }

    // epilogue
#pragma unroll
    for (int mt = 0; mt < 4; mt++)
#pragma unroll
        for (int nt = 0; nt < 4; nt++) {
            const int row = m0 + wm * 64 + mt * 16 + g;
            const int col = n0 + wn * 32 + nt * 8 + tg * 2;
            float* c = acc[mt][nt];
            if (MODE == 0) {
                const float2 b2 = *(const float2*)(bias + col);
                *(float2*)(C + (size_t)row * ldc + col) =
                    make_float2(c[0] + b2.x, c[1] + b2.y);
                *(float2*)(C + (size_t)(row + 8) * ldc + col) =
                    make_float2(c[2] + b2.x, c[3] + b2.y);
            } else if (MODE == 2) {
                float2 v0, v1;
                v0.x = (col     <= row    ) ? c[0] * scale : -1e9f;
                v0.y = (col + 1 <= row    ) ? c[1] * scale : -1e9f;
                v1.x = (col     <= row + 8) ? c[2] * scale : -1e9f;
                v1.y = (col + 1 <= row + 8) ? c[3] * scale : -1e9f;
                *(float2*)(C + (size_t)row * ldc + col)       = v0;
                *(float2*)(C + (size_t)(row + 8) * ldc + col) = v1;
            } else {
                *(float2*)(C + (size_t)row * ldc + col)       = make_float2(c[0], c[1]);
                *(float2*)(C + (size_t)(row + 8) * ldc + col) = make_float2(c[2], c[3]);
            }
        }
}

// ---------------------------------------------------------------------------
// Transpose v[16384][1024] -> vt[1024][16384] (coalesced both sides)
// ---------------------------------------------------------------------------
__global__ __launch_bounds__(256) void transpose_k(
    const float* __restrict__ in, float* __restrict__ out)
{
    __shared__ float t[32][33];
    const int x0 = blockIdx.x * 32;  // col in input
    const int y0 = blockIdx.y * 32;  // row in input
    const int tx = threadIdx.x & 31;
    const int ty = threadIdx.x >> 5;
#pragma unroll
    for (int j = 0; j < 32; j += 8)
        t[ty + j][tx] = in[(size_t)(y0 + ty + j) * H_ + x0 + tx];
    __syncthreads();
#pragma unroll
    for (int j = 0; j < 32; j += 8)
        out[(size_t)(x0 + ty + j) * (B_ * S_) + y0 + tx] = t[tx][ty + j];
}

// ---------------------------------------------------------------------------
// Row softmax on scores, in place, causal prefix only.
// ---------------------------------------------------------------------------
__global__ __launch_bounds__(256) void softmax_rows(float* __restrict__ P) {
    const int r = blockIdx.x;
    const int m = r & (S_ - 1);
    float* row = P + (size_t)r * S_;
    const int KB = ((m >> 7) + 1) << 7;  // round_up(m+1, 128)

    __shared__ float buf[S_];
    __shared__ float red[8];
    const int tid = threadIdx.x;

    float mx = -3.4e38f;
    for (int i = tid; i < KB; i += 256) {
        float v = row[i];
        buf[i] = v;
        mx = fmaxf(mx, v);
    }
#pragma unroll
    for (int o = 16; o; o >>= 1) mx = fmaxf(mx, __shfl_xor_sync(0xffffffffu, mx, o));
    if ((tid & 31) == 0) red[tid >> 5] = mx;
    __syncthreads();
    if (tid == 0) {
        float t = red[0];
#pragma unroll
        for (int i = 1; i < 8; i++) t = fmaxf(t, red[i]);
        red[0] = t;
    }
    __syncthreads();
    mx = red[0];
    __syncthreads();

    float sm = 0.f;
    for (int i = tid; i < KB; i += 256) {
        float e = expf(buf[i] - mx);
        buf[i] = e;
        sm += e;
    }
#pragma unroll
    for (int o = 16; o; o >>= 1) sm += __shfl_xor_sync(0xffffffffu, sm, o);
    __syncthreads();
    if ((tid & 31) == 0) red[tid >> 5] = sm;
    __syncthreads();
    if (tid == 0) {
        float t = 0.f;
#pragma unroll
        for (int i = 0; i < 8; i++) t += red[i];
        red[0] = t;
    }
    __syncthreads();
    const float inv = 1.f / red[0];

    for (int i = tid; i < KB; i += 256) row[i] = buf[i] * inv;
}

// ---------------------------------------------------------------------------
// Launch pipeline (graph-capturable)
// ---------------------------------------------------------------------------
extern "C" void kernel_launch(void* const* d_in, const int* in_sizes, int n_in,
                              void* d_out, int out_size)
{
    (void)in_sizes; (void)n_in; (void)out_size;
    const float* x  = (const float*)d_in[0];
    const float* Wq = (const float*)d_in[1];
    const float* bq = (const float*)d_in[2];
    const float* Wk = (const float*)d_in[3];
    const float* bk = (const float*)d_in[4];
    const float* Wv = (const float*)d_in[5];
    const float* bv = (const float*)d_in[6];
    float* out = (float*)d_out;

    float *q, *k, *v, *vt, *p;
    cudaGetSymbolAddress((void**)&q,  g_q);
    cudaGetSymbolAddress((void**)&k,  g_k);
    cudaGetSymbolAddress((void**)&v,  g_v);
    cudaGetSymbolAddress((void**)&vt, g_vt);
    cudaGetSymbolAddress((void**)&p,  g_p);

    cudaFuncSetAttribute(gemm_nt<0>, cudaFuncAttributeMaxDynamicSharedMemorySize, SMEM_BYTES);
    cudaFuncSetAttribute(gemm_nt<2>, cudaFuncAttributeMaxDynamicSharedMemorySize, SMEM_BYTES);
    cudaFuncSetAttribute(gemm_nt<3>, cudaFuncAttributeMaxDynamicSharedMemorySize, SMEM_BYTES);

    const dim3 blk(256);
    const int M = B_ * S_;  // 16384

    // 1) QKV projections
    const dim3 gq(H_ / BN, M / BM, 1);  // (8, 128)
    gemm_nt<0><<<gq, blk, SMEM_BYTES>>>(x, Wq, bq, q, D_, D_, D_, H_, 0, 0, 0, 1.f);
    gemm_nt<0><<<gq, blk, SMEM_BYTES>>>(x, Wk, bk, k, D_, D_, D_, H_, 0, 0, 0, 1.f);
    gemm_nt<0><<<gq, blk, SMEM_BYTES>>>(x, Wv, bv, v, D_, D_, D_, H_, 0, 0, 0, 1.f);

    // 1b) V^T for the PV GEMM
    transpose_k<<<dim3(H_ / 32, M / 32), blk>>>(v, vt);

    // 2) Scores: per batch, Q @ K^T / 32, causal
    const dim3 gs(S_ / BN, S_ / BM, B_);  // (16, 16, 8)
    gemm_nt<2><<<gs, blk, SMEM_BYTES>>>(q, k, nullptr, p, H_, H_, H_, S_,
                                        (long)S_ * H_, (long)S_ * H_, (long)S_ * S_,
                                        0.03125f);

    // 3) Row softmax (causal prefix)
    softmax_rows<<<M, blk>>>(p);

    // 4) O = P @ V  (B = V^T, NT form, causal k-limit)
    const dim3 gp(H_ / BN, S_ / BM, B_);  // (8, 16, 8)
    gemm_nt<3><<<gp, blk, SMEM_BYTES>>>(p, vt, nullptr, out, S_, S_, B_ * S_, H_,
                                        (long)S_ * S_, (long)S_, (long)S_ * H_, 1.f);
}

// round 4
// speedup vs baseline: 2.5247x; 1.2899x over previous
#include <cuda_runtime.h>
#include <cuda_bf16.h>
#include <cstdint>
#include <math.h>

static constexpr int B_ = 8, S_ = 2048, D_ = 1024, H_ = 1024;

// Tiling: 128x128 CTA tile, BK=32 (fp32 cols), bf16 hi/lo planes in SMEM.
static constexpr int BM = 128, BN = 128, BK = 32;
static constexpr int ROWB = 80;                  // bytes per row per plane (64 data + 16 pad)
static constexpr int PL   = BM * ROWB;           // 10240 bytes per plane
static constexpr int BUFB = 4 * PL;              // A_h, A_l, B_h, B_l
static constexpr int SMEM_BYTES = 2 * BUFB;      // 81920 (double buffered)

// Device scratch (allocation-free rule: __device__ globals)
__device__ float g_q[(size_t)B_ * S_ * H_];
__device__ float g_k[(size_t)B_ * S_ * H_];
__device__ float g_v[(size_t)B_ * S_ * H_];
__device__ float g_vt[(size_t)B_ * S_ * H_];
__device__ float g_p[(size_t)B_ * S_ * S_];

// ---------------------------------------------------------------------------
// bf16 hi/lo split of a float4 -> two packed uint2 (4 bf16 each)
// ---------------------------------------------------------------------------
__device__ __forceinline__ void cvt_hilo(float4 v, uint2& h, uint2& l) {
    __nv_bfloat162 h0 = __floats2bfloat162_rn(v.x, v.y);
    __nv_bfloat162 h1 = __floats2bfloat162_rn(v.z, v.w);
    float rx = v.x - __bfloat162float(h0.x);
    float ry = v.y - __bfloat162float(h0.y);
    float rz = v.z - __bfloat162float(h1.x);
    float rw = v.w - __bfloat162float(h1.y);
    __nv_bfloat162 l0 = __floats2bfloat162_rn(rx, ry);
    __nv_bfloat162 l1 = __floats2bfloat162_rn(rz, rw);
    h.x = *reinterpret_cast<uint32_t*>(&h0);
    h.y = *reinterpret_cast<uint32_t*>(&h1);
    l.x = *reinterpret_cast<uint32_t*>(&l0);
    l.y = *reinterpret_cast<uint32_t*>(&l1);
}

__device__ __forceinline__ void mma16(float* d, const uint32_t* a, const uint32_t* b) {
    asm volatile(
        "mma.sync.aligned.m16n8k16.row.col.f32.bf16.bf16.f32 "
        "{%0,%1,%2,%3},{%4,%5,%6,%7},{%8,%9},{%0,%1,%2,%3};"
        : "+f"(d[0]), "+f"(d[1]), "+f"(d[2]), "+f"(d[3])
        : "r"(a[0]), "r"(a[1]), "r"(a[2]), "r"(a[3]), "r"(b[0]), "r"(b[1]));
}

// ---------------------------------------------------------------------------
// Per-buffer compute: 2 k16 steps, warp tile 64x32, bf16x3.
// ---------------------------------------------------------------------------
__device__ __forceinline__ void compute_tile(
    const char* buf, float (&acc)[4][4][4], int aoff0, int boff0)
{
#pragma unroll
    for (int ks = 0; ks < 2; ks++) {
        const int kb = ks * 32;  // byte offset of this k16 step
        uint32_t bh[4][2], bl[4][2];
#pragma unroll
        for (int nt = 0; nt < 4; nt++) {
            const char* pbh = buf + 2 * PL + boff0 + nt * 8 * ROWB + kb;
            bh[nt][0] = *(const uint32_t*)pbh;
            bh[nt][1] = *(const uint32_t*)(pbh + 16);
            bl[nt][0] = *(const uint32_t*)(pbh + PL);
            bl[nt][1] = *(const uint32_t*)(pbh + PL + 16);
        }
#pragma unroll
        for (int mt = 0; mt < 4; mt++) {
            const char* pah = buf + aoff0 + mt * 16 * ROWB + kb;
            uint32_t ah[4], al[4];
            ah[0] = *(const uint32_t*)pah;
            ah[1] = *(const uint32_t*)(pah + 8 * ROWB);
            ah[2] = *(const uint32_t*)(pah + 16);
            ah[3] = *(const uint32_t*)(pah + 8 * ROWB + 16);
            al[0] = *(const uint32_t*)(pah + PL);
            al[1] = *(const uint32_t*)(pah + PL + 8 * ROWB);
            al[2] = *(const uint32_t*)(pah + PL + 16);
            al[3] = *(const uint32_t*)(pah + PL + 8 * ROWB + 16);
#pragma unroll
            for (int nt = 0; nt < 4; nt++) {
                mma16(acc[mt][nt], ah, bh[nt]);  // a_hi * b_hi
                mma16(acc[mt][nt], ah, bl[nt]);  // a_hi * b_lo
                mma16(acc[mt][nt], al, bh[nt]);  // a_lo * b_hi
            }
        }
    }
}

// ---------------------------------------------------------------------------
// NT GEMM: C[m,n] = sum_k A[m,k]*B[n,k], bf16x3, double-buffered.
// MODE 0: + bias[n]           (QKV projections)
// MODE 2: scale + causal mask (scores; skips fully-masked tiles)
// MODE 3: plain, Kend = m0+BM (PV with causal k-limit; B = V^T)
// ---------------------------------------------------------------------------
template <int MODE>
__global__ __launch_bounds__(256, 2) void gemm_nt(
    const float* __restrict__ A, const float* __restrict__ Bm,
    const float* __restrict__ bias, float* __restrict__ C,
    int K, int lda, int ldb, int ldc,
    long sAz, long sBz, long sCz, float scale)
{
    const int m0 = blockIdx.y * BM;
    const int n0 = blockIdx.x * BN;
    if (MODE == 2 && n0 > m0) return;  // fully masked tile

    const int z = blockIdx.z;
    A  += (size_t)z * sAz;
    Bm += (size_t)z * sBz;
    C  += (size_t)z * sCz;

    extern __shared__ char smx[];

    const int tid  = threadIdx.x;
    const int lane = tid & 31;
    const int wid  = tid >> 5;
    const int wm   = wid >> 2;   // 0..1 (64 rows)
    const int wn   = wid & 3;    // 0..3 (32 cols)
    const int g    = lane >> 2;
    const int tg   = lane & 3;
    const int aoff0 = (wm * 64 + g) * ROWB + tg * 4;
    const int boff0 = (wn * 32 + g) * ROWB + tg * 4;

    const int Kend = (MODE == 3) ? (m0 + BM) : K;
    const int KT   = Kend / BK;

    // Global load mapping: row lr+32j (j=0..3), float4 column lc (BK=32 -> 8 f4/row)
    const int lr = tid >> 3;
    const int lc = tid & 7;
    const float* pA = A  + (size_t)(m0 + lr) * lda + lc * 4;
    const float* pB = Bm + (size_t)(n0 + lr) * ldb + lc * 4;
    const int stoff = lr * ROWB + lc * 8;  // byte offset within plane

    float acc[4][4][4];
#pragma unroll
    for (int i = 0; i < 4; i++)
#pragma unroll
        for (int j = 0; j < 4; j++)
#pragma unroll
            for (int e = 0; e < 4; e++) acc[i][j][e] = 0.f;

    // prologue: tile 0
    {
        char* b0 = smx;
#pragma unroll
        for (int j = 0; j < 4; j++) {
            float4 va = *(const float4*)(pA + (size_t)(32 * j) * lda);
            float4 vb = *(const float4*)(pB + (size_t)(32 * j) * ldb);
            uint2 h, l;
            char* d = b0 + stoff + j * 32 * ROWB;
            cvt_hilo(va, h, l);
            *(uint2*)(d)      = h;
            *(uint2*)(d + PL) = l;
            cvt_hilo(vb, h, l);
            *(uint2*)(d + 2 * PL) = h;
            *(uint2*)(d + 3 * PL) = l;
        }
    }
    __syncthreads();

    for (int kt = 0; kt < KT; kt++) {
        const int cur = kt & 1;
        float4 ra[4], rb[4];
        if (kt + 1 < KT) {
            const float* qA = pA + (kt + 1) * BK;
            const float* qB = pB + (kt + 1) * BK;
#pragma unroll
            for (int j = 0; j < 4; j++) {
                ra[j] = *(const float4*)(qA + (size_t)(32 * j) * lda);
                rb[j] = *(const float4*)(qB + (size_t)(32 * j) * ldb);
            }
        }

        compute_tile(smx + cur * BUFB, acc, aoff0, boff0);

        if (kt + 1 < KT) {
            char* nb = smx + (1 - cur) * BUFB;
#pragma unroll
            for (int j = 0; j < 4; j++) {
                uint2 h, l;
                char* d = nb + stoff + j * 32 * ROWB;
                cvt_hilo(ra[j], h, l);
                *(uint2*)(d)      = h;
                *(uint2*)(d + PL) = l;
                cvt_hilo(rb[j], h, l);
                *(uint2*)(d + 2 * PL) = h;
                *(uint2*)(d + 3 * PL) = l;
            }
            __syncthreads();
        }
    }

    // epilogue
#pragma unroll
    for (int mt = 0; mt < 4; mt++)
#pragma unroll
        for (int nt = 0; nt < 4; nt++) {
            const int row = m0 + wm * 64 + mt * 16 + g;
            const int col = n0 + wn * 32 + nt * 8 + tg * 2;
            float* c = acc[mt][nt];
            if (MODE == 0) {
                const float2 b2 = *(const float2*)(bias + col);
                *(float2*)(C + (size_t)row * ldc + col) =
                    make_float2(c[0] + b2.x, c[1] + b2.y);
                *(float2*)(C + (size_t)(row + 8) * ldc + col) =
                    make_float2(c[2] + b2.x, c[3] + b2.y);
            } else if (MODE == 2) {
                float2 v0, v1;
                v0.x = (col     <= row    ) ? c[0] * scale : -1e9f;
                v0.y = (col + 1 <= row    ) ? c[1] * scale : -1e9f;
                v1.x = (col     <= row + 8) ? c[2] * scale : -1e9f;
                v1.y = (col + 1 <= row + 8) ? c[3] * scale : -1e9f;
                *(float2*)(C + (size_t)row * ldc + col)       = v0;
                *(float2*)(C + (size_t)(row + 8) * ldc + col) = v1;
            } else {
                *(float2*)(C + (size_t)row * ldc + col)       = make_float2(c[0], c[1]);
                *(float2*)(C + (size_t)(row + 8) * ldc + col) = make_float2(c[2], c[3]);
            }
        }
}

// ---------------------------------------------------------------------------
// Transpose v[16384][1024] -> vt[1024][16384]
// ---------------------------------------------------------------------------
__global__ __launch_bounds__(256) void transpose_k(
    const float* __restrict__ in, float* __restrict__ out)
{
    __shared__ float t[32][33];
    const int x0 = blockIdx.x * 32;
    const int y0 = blockIdx.y * 32;
    const int tx = threadIdx.x & 31;
    const int ty = threadIdx.x >> 5;
#pragma unroll
    for (int j = 0; j < 32; j += 8)
        t[ty + j][tx] = in[(size_t)(y0 + ty + j) * H_ + x0 + tx];
    __syncthreads();
#pragma unroll
    for (int j = 0; j < 32; j += 8)
        out[(size_t)(x0 + ty + j) * (B_ * S_) + y0 + tx] = t[tx][ty + j];
}

// ---------------------------------------------------------------------------
// Row softmax, in place, causal prefix only.
// ---------------------------------------------------------------------------
__global__ __launch_bounds__(256) void softmax_rows(float* __restrict__ P) {
    const int r = blockIdx.x;
    const int m = r & (S_ - 1);
    float* row = P + (size_t)r * S_;
    const int KB = ((m >> 7) + 1) << 7;

    __shared__ float buf[S_];
    __shared__ float red[8];
    const int tid = threadIdx.x;

    float mx = -3.4e38f;
    for (int i = tid; i < KB; i += 256) {
        float v = row[i];
        buf[i] = v;
        mx = fmaxf(mx, v);
    }
#pragma unroll
    for (int o = 16; o; o >>= 1) mx = fmaxf(mx, __shfl_xor_sync(0xffffffffu, mx, o));
    if ((tid & 31) == 0) red[tid >> 5] = mx;
    __syncthreads();
    if (tid == 0) {
        float t = red[0];
#pragma unroll
        for (int i = 1; i < 8; i++) t = fmaxf(t, red[i]);
        red[0] = t;
    }
    __syncthreads();
    mx = red[0];
    __syncthreads();

    float sm = 0.f;
    for (int i = tid; i < KB; i += 256) {
        float e = expf(buf[i] - mx);
        buf[i] = e;
        sm += e;
    }
#pragma unroll
    for (int o = 16; o; o >>= 1) sm += __shfl_xor_sync(0xffffffffu, sm, o);
    __syncthreads();
    if ((tid & 31) == 0) red[tid >> 5] = sm;
    __syncthreads();
    if (tid == 0) {
        float t = 0.f;
#pragma unroll
        for (int i = 0; i < 8; i++) t += red[i];
        red[0] = t;
    }
    __syncthreads();
    const float inv = 1.f / red[0];

    for (int i = tid; i < KB; i += 256) row[i] = buf[i] * inv;
}

// ---------------------------------------------------------------------------
// Launch pipeline (graph-capturable)
// ---------------------------------------------------------------------------
extern "C" void kernel_launch(void* const* d_in, const int* in_sizes, int n_in,
                              void* d_out, int out_size)
{
    (void)in_sizes; (void)n_in; (void)out_size;
    const float* x  = (const float*)d_in[0];
    const float* Wq = (const float*)d_in[1];
    const float* bq = (const float*)d_in[2];
    const float* Wk = (const float*)d_in[3];
    const float* bk = (const float*)d_in[4];
    const float* Wv = (const float*)d_in[5];
    const float* bv = (const float*)d_in[6];
    float* out = (float*)d_out;

    float *q, *k, *v, *vt, *p;
    cudaGetSymbolAddress((void**)&q,  g_q);
    cudaGetSymbolAddress((void**)&k,  g_k);
    cudaGetSymbolAddress((void**)&v,  g_v);
    cudaGetSymbolAddress((void**)&vt, g_vt);
    cudaGetSymbolAddress((void**)&p,  g_p);

    cudaFuncSetAttribute(gemm_nt<0>, cudaFuncAttributeMaxDynamicSharedMemorySize, SMEM_BYTES);
    cudaFuncSetAttribute(gemm_nt<2>, cudaFuncAttributeMaxDynamicSharedMemorySize, SMEM_BYTES);
    cudaFuncSetAttribute(gemm_nt<3>, cudaFuncAttributeMaxDynamicSharedMemorySize, SMEM_BYTES);

    const dim3 blk(256);
    const int M = B_ * S_;  // 16384

    // 1) QKV projections
    const dim3 gq(H_ / BN, M / BM, 1);  // (8, 128)
    gemm_nt<0><<<gq, blk, SMEM_BYTES>>>(x, Wq, bq, q, D_, D_, D_, H_, 0, 0, 0, 1.f);
    gemm_nt<0><<<gq, blk, SMEM_BYTES>>>(x, Wk, bk, k, D_, D_, D_, H_, 0, 0, 0, 1.f);
    gemm_nt<0><<<gq, blk, SMEM_BYTES>>>(x, Wv, bv, v, D_, D_, D_, H_, 0, 0, 0, 1.f);

    // 1b) V^T for the PV GEMM
    transpose_k<<<dim3(H_ / 32, M / 32), blk>>>(v, vt);

    // 2) Scores: per batch, Q @ K^T / 32, causal
    const dim3 gs(S_ / BN, S_ / BM, B_);  // (16, 16, 8)
    gemm_nt<2><<<gs, blk, SMEM_BYTES>>>(q, k, nullptr, p, H_, H_, H_, S_,
                                        (long)S_ * H_, (long)S_ * H_, (long)S_ * S_,
                                        0.03125f);

    // 3) Row softmax (causal prefix)
    softmax_rows<<<M, blk>>>(p);

    // 4) O = P @ V  (B = V^T, NT form, causal k-limit)
    const dim3 gp(H_ / BN, S_ / BM, B_);  // (8, 16, 8)
    gemm_nt<3><<<gp, blk, SMEM_BYTES>>>(p, vt, nullptr, out, S_, S_, B_ * S_, H_,
                                        (long)S_ * S_, (long)S_, (long)S_ * H_, 1.f);
}

// round 5
// speedup vs baseline: 3.0819x; 1.2207x over previous
#include <cuda_runtime.h>
#include <cuda_fp16.h>
#include <cstdint>
#include <math.h>

static constexpr int B_ = 8, S_ = 2048, D_ = 1024, H_ = 1024;

// Tiling: 128x128 CTA tile, BK=32 (fp32 cols). fp16 planes: A_h, B_h, B_l.
static constexpr int BM = 128, BN = 128, BK = 32;
static constexpr int ROWB = 80;                  // 64 data bytes + 16 pad
static constexpr int PL   = BM * ROWB;           // 10240 bytes per plane
static constexpr int BUFB = 3 * PL;              // 30720 per stage
static constexpr int SMEM_BYTES = 2 * BUFB;      // 61440, double buffered

// Device scratch (allocation-free rule: __device__ globals)
__device__ float g_q[(size_t)B_ * S_ * H_];
__device__ float g_k[(size_t)B_ * S_ * H_];
__device__ float g_v[(size_t)B_ * S_ * H_];
__device__ float g_vt[(size_t)B_ * S_ * H_];
__device__ float g_p[(size_t)B_ * S_ * S_];

// ---------------------------------------------------------------------------
// helpers
// ---------------------------------------------------------------------------
__device__ __forceinline__ uint32_t smem_u32(const void* p) {
    uint32_t a;
    asm("{ .reg .u64 t; cvta.to.shared.u64 t, %1; cvt.u32.u64 %0, t; }"
        : "=r"(a) : "l"(p));
    return a;
}

__device__ __forceinline__ uint2 cvt4h(float4 v) {
    __half2 a = __floats2half2_rn(v.x, v.y);
    __half2 b = __floats2half2_rn(v.z, v.w);
    uint2 r;
    r.x = *reinterpret_cast<uint32_t*>(&a);
    r.y = *reinterpret_cast<uint32_t*>(&b);
    return r;
}

__device__ __forceinline__ void cvt4hl(float4 v, uint2& h, uint2& l) {
    __half2 h0 = __floats2half2_rn(v.x, v.y);
    __half2 h1 = __floats2half2_rn(v.z, v.w);
    float rx = v.x - __half2float(__low2half(h0));
    float ry = v.y - __half2float(__high2half(h0));
    float rz = v.z - __half2float(__low2half(h1));
    float rw = v.w - __half2float(__high2half(h1));
    __half2 l0 = __floats2half2_rn(rx, ry);
    __half2 l1 = __floats2half2_rn(rz, rw);
    h.x = *reinterpret_cast<uint32_t*>(&h0);
    h.y = *reinterpret_cast<uint32_t*>(&h1);
    l.x = *reinterpret_cast<uint32_t*>(&l0);
    l.y = *reinterpret_cast<uint32_t*>(&l1);
}

__device__ __forceinline__ void mma16(float* d, const uint32_t* a, const uint32_t* b) {
    asm volatile(
        "mma.sync.aligned.m16n8k16.row.col.f32.f16.f16.f32 "
        "{%0,%1,%2,%3},{%4,%5,%6,%7},{%8,%9},{%0,%1,%2,%3};"
        : "+f"(d[0]), "+f"(d[1]), "+f"(d[2]), "+f"(d[3])
        : "r"(a[0]), "r"(a[1]), "r"(a[2]), "r"(a[3]), "r"(b[0]), "r"(b[1]));
}

__device__ __forceinline__ void ldsm4(uint32_t* r, uint32_t addr) {
    asm volatile(
        "ldmatrix.sync.aligned.m8n8.x4.shared.b16 {%0,%1,%2,%3}, [%4];"
        : "=r"(r[0]), "=r"(r[1]), "=r"(r[2]), "=r"(r[3]) : "r"(addr));
}

// ---------------------------------------------------------------------------
// Per-stage compute: 2 k16 steps, warp tile 64x32, fp16x2 via ldmatrix.
// aBase/bBase are lane-resolved byte offsets within a stage.
// ---------------------------------------------------------------------------
__device__ __forceinline__ void compute_tile(
    uint32_t buf, float (&acc)[4][4][4], uint32_t aBase, uint32_t bBase)
{
#pragma unroll
    for (int ks = 0; ks < 2; ks++) {
        const uint32_t kb = ks * 32;
        uint32_t bh[2][4], bl[2][4];
#pragma unroll
        for (int ntp = 0; ntp < 2; ntp++) {
            const uint32_t ba = buf + PL + bBase + ntp * 16 * ROWB + kb;
            ldsm4(bh[ntp], ba);
            ldsm4(bl[ntp], ba + PL);
        }
#pragma unroll
        for (int mt = 0; mt < 4; mt++) {
            uint32_t af[4];
            ldsm4(af, buf + aBase + mt * 16 * ROWB + kb);
#pragma unroll
            for (int nt = 0; nt < 4; nt++) {
                const int ntp = nt >> 1, s = nt & 1;
                uint32_t b0[2] = {bh[ntp][s], bh[ntp][s + 2]};
                uint32_t b1[2] = {bl[ntp][s], bl[ntp][s + 2]};
                mma16(acc[mt][nt], af, b0);  // a_hi * b_hi
                mma16(acc[mt][nt], af, b1);  // a_hi * b_lo
            }
        }
    }
}

// ---------------------------------------------------------------------------
// NT GEMM: C[m,n] = sum_k A[m,k]*B[n,k], fp16x2, double-buffered.
// MODE 0: + bias[n]           (QKV projections)
// MODE 2: scale + causal mask (scores; skips fully-masked tiles)
// MODE 3: plain, Kend = m0+BM (PV with causal k-limit; B = V^T)
// ---------------------------------------------------------------------------
template <int MODE>
__global__ __launch_bounds__(256, 2) void gemm_nt(
    const float* __restrict__ A, const float* __restrict__ Bm,
    const float* __restrict__ bias, float* __restrict__ C,
    int K, int lda, int ldb, int ldc,
    long sAz, long sBz, long sCz, float scale)
{
    const int m0 = blockIdx.y * BM;
    const int n0 = blockIdx.x * BN;
    if (MODE == 2 && n0 > m0) return;  // fully masked tile

    const int z = blockIdx.z;
    A  += (size_t)z * sAz;
    Bm += (size_t)z * sBz;
    C  += (size_t)z * sCz;

    extern __shared__ char smx[];
    const uint32_t smb = smem_u32(smx);

    const int tid  = threadIdx.x;
    const int lane = tid & 31;
    const int wid  = tid >> 5;
    const int wm   = wid >> 2;   // 0..1 (64 rows)
    const int wn   = wid & 3;    // 0..3 (32 cols)
    const int g    = lane >> 2;
    const int tg   = lane & 3;

    // ldmatrix lane addressing
    const uint32_t lq = lane & 15, lh = lane >> 4;
    const uint32_t aBase = (wm * 64 + lq) * ROWB + lh * 16;
    const uint32_t bBase = (wn * 32 + lq) * ROWB + lh * 16;

    const int Kend = (MODE == 3) ? (m0 + BM) : K;
    const int KT   = Kend / BK;

    // Global load mapping: rows lr+32j (j=0..3), float4 column lc
    const int lr = tid >> 3;
    const int lc = tid & 7;
    const float* pA = A  + (size_t)(m0 + lr) * lda + lc * 4;
    const float* pB = Bm + (size_t)(n0 + lr) * ldb + lc * 4;
    const int stoff = lr * ROWB + lc * 8;  // byte offset within plane

    float acc[4][4][4];
#pragma unroll
    for (int i = 0; i < 4; i++)
#pragma unroll
        for (int j = 0; j < 4; j++)
#pragma unroll
            for (int e = 0; e < 4; e++) acc[i][j][e] = 0.f;

    // prologue: stage 0
    {
        char* b0 = smx;
#pragma unroll
        for (int j = 0; j < 4; j++) {
            float4 va = *(const float4*)(pA + (size_t)(32 * j) * lda);
            float4 vb = *(const float4*)(pB + (size_t)(32 * j) * ldb);
            char* d = b0 + stoff + j * 32 * ROWB;
            *(uint2*)d = cvt4h(va);
            uint2 h, l;
            cvt4hl(vb, h, l);
            *(uint2*)(d + PL)     = h;
            *(uint2*)(d + 2 * PL) = l;
        }
    }
    __syncthreads();

    for (int kt = 0; kt < KT; kt++) {
        const int cur = kt & 1;
        float4 ra[4], rb[4];
        if (kt + 1 < KT) {
            const float* qA = pA + (kt + 1) * BK;
            const float* qB = pB + (kt + 1) * BK;
#pragma unroll
            for (int j = 0; j < 4; j++) {
                ra[j] = *(const float4*)(qA + (size_t)(32 * j) * lda);
                rb[j] = *(const float4*)(qB + (size_t)(32 * j) * ldb);
            }
        }

        compute_tile(smb + cur * BUFB, acc, aBase, bBase);

        if (kt + 1 < KT) {
            char* nb = smx + (1 - cur) * BUFB;
#pragma unroll
            for (int j = 0; j < 4; j++) {
                char* d = nb + stoff + j * 32 * ROWB;
                *(uint2*)d = cvt4h(ra[j]);
                uint2 h, l;
                cvt4hl(rb[j], h, l);
                *(uint2*)(d + PL)     = h;
                *(uint2*)(d + 2 * PL) = l;
            }
            __syncthreads();
        }
    }

    // epilogue
#pragma unroll
    for (int mt = 0; mt < 4; mt++)
#pragma unroll
        for (int nt = 0; nt < 4; nt++) {
            const int row = m0 + wm * 64 + mt * 16 + g;
            const int col = n0 + wn * 32 + nt * 8 + tg * 2;
            float* c = acc[mt][nt];
            if (MODE == 0) {
                const float2 b2 = *(const float2*)(bias + col);
                *(float2*)(C + (size_t)row * ldc + col) =
                    make_float2(c[0] + b2.x, c[1] + b2.y);
                *(float2*)(C + (size_t)(row + 8) * ldc + col) =
                    make_float2(c[2] + b2.x, c[3] + b2.y);
            } else if (MODE == 2) {
                float2 v0, v1;
                v0.x = (col     <= row    ) ? c[0] * scale : -1e9f;
                v0.y = (col + 1 <= row    ) ? c[1] * scale : -1e9f;
                v1.x = (col     <= row + 8) ? c[2] * scale : -1e9f;
                v1.y = (col + 1 <= row + 8) ? c[3] * scale : -1e9f;
                *(float2*)(C + (size_t)row * ldc + col)       = v0;
                *(float2*)(C + (size_t)(row + 8) * ldc + col) = v1;
            } else {
                *(float2*)(C + (size_t)row * ldc + col)       = make_float2(c[0], c[1]);
                *(float2*)(C + (size_t)(row + 8) * ldc + col) = make_float2(c[2], c[3]);
            }
        }
}

// ---------------------------------------------------------------------------
// Transpose v[16384][1024] -> vt[1024][16384]
// ---------------------------------------------------------------------------
__global__ __launch_bounds__(256) void transpose_k(
    const float* __restrict__ in, float* __restrict__ out)
{
    __shared__ float t[32][33];
    const int x0 = blockIdx.x * 32;
    const int y0 = blockIdx.y * 32;
    const int tx = threadIdx.x & 31;
    const int ty = threadIdx.x >> 5;
#pragma unroll
    for (int j = 0; j < 32; j += 8)
        t[ty + j][tx] = in[(size_t)(y0 + ty + j) * H_ + x0 + tx];
    __syncthreads();
#pragma unroll
    for (int j = 0; j < 32; j += 8)
        out[(size_t)(x0 + ty + j) * (B_ * S_) + y0 + tx] = t[tx][ty + j];
}

// ---------------------------------------------------------------------------
// Row softmax, in place, causal prefix only.
// ---------------------------------------------------------------------------
__global__ __launch_bounds__(256) void softmax_rows(float* __restrict__ P) {
    const int r = blockIdx.x;
    const int m = r & (S_ - 1);
    float* row = P + (size_t)r * S_;
    const int KB = ((m >> 7) + 1) << 7;

    __shared__ float buf[S_];
    __shared__ float red[8];
    const int tid = threadIdx.x;

    float mx = -3.4e38f;
    for (int i = tid; i < KB; i += 256) {
        float v = row[i];
        buf[i] = v;
        mx = fmaxf(mx, v);
    }
#pragma unroll
    for (int o = 16; o; o >>= 1) mx = fmaxf(mx, __shfl_xor_sync(0xffffffffu, mx, o));
    if ((tid & 31) == 0) red[tid >> 5] = mx;
    __syncthreads();
    if (tid == 0) {
        float t = red[0];
#pragma unroll
        for (int i = 1; i < 8; i++) t = fmaxf(t, red[i]);
        red[0] = t;
    }
    __syncthreads();
    mx = red[0];
    __syncthreads();

    float sm = 0.f;
    for (int i = tid; i < KB; i += 256) {
        float e = expf(buf[i] - mx);
        buf[i] = e;
        sm += e;
    }
#pragma unroll
    for (int o = 16; o; o >>= 1) sm += __shfl_xor_sync(0xffffffffu, sm, o);
    __syncthreads();
    if ((tid & 31) == 0) red[tid >> 5] = sm;
    __syncthreads();
    if (tid == 0) {
        float t = 0.f;
#pragma unroll
        for (int i = 0; i < 8; i++) t += red[i];
        red[0] = t;
    }
    __syncthreads();
    const float inv = 1.f / red[0];

    for (int i = tid; i < KB; i += 256) row[i] = buf[i] * inv;
}

// ---------------------------------------------------------------------------
// Launch pipeline (graph-capturable)
// ---------------------------------------------------------------------------
extern "C" void kernel_launch(void* const* d_in, const int* in_sizes, int n_in,
                              void* d_out, int out_size)
{
    (void)in_sizes; (void)n_in; (void)out_size;
    const float* x  = (const float*)d_in[0];
    const float* Wq = (const float*)d_in[1];
    const float* bq = (const float*)d_in[2];
    const float* Wk = (const float*)d_in[3];
    const float* bk = (const float*)d_in[4];
    const float* Wv = (const float*)d_in[5];
    const float* bv = (const float*)d_in[6];
    float* out = (float*)d_out;

    float *q, *k, *v, *vt, *p;
    cudaGetSymbolAddress((void**)&q,  g_q);
    cudaGetSymbolAddress((void**)&k,  g_k);
    cudaGetSymbolAddress((void**)&v,  g_v);
    cudaGetSymbolAddress((void**)&vt, g_vt);
    cudaGetSymbolAddress((void**)&p,  g_p);

    cudaFuncSetAttribute(gemm_nt<0>, cudaFuncAttributeMaxDynamicSharedMemorySize, SMEM_BYTES);
    cudaFuncSetAttribute(gemm_nt<2>, cudaFuncAttributeMaxDynamicSharedMemorySize, SMEM_BYTES);
    cudaFuncSetAttribute(gemm_nt<3>, cudaFuncAttributeMaxDynamicSharedMemorySize, SMEM_BYTES);

    const dim3 blk(256);
    const int M = B_ * S_;  // 16384

    // 1) QKV projections
    const dim3 gq(H_ / BN, M / BM, 1);  // (8, 128)
    gemm_nt<0><<<gq, blk, SMEM_BYTES>>>(x, Wq, bq, q, D_, D_, D_, H_, 0, 0, 0, 1.f);
    gemm_nt<0><<<gq, blk, SMEM_BYTES>>>(x, Wk, bk, k, D_, D_, D_, H_, 0, 0, 0, 1.f);
    gemm_nt<0><<<gq, blk, SMEM_BYTES>>>(x, Wv, bv, v, D_, D_, D_, H_, 0, 0, 0, 1.f);

    // 1b) V^T for the PV GEMM
    transpose_k<<<dim3(H_ / 32, M / 32), blk>>>(v, vt);

    // 2) Scores: per batch, Q @ K^T / 32, causal
    const dim3 gs(S_ / BN, S_ / BM, B_);  // (16, 16, 8)
    gemm_nt<2><<<gs, blk, SMEM_BYTES>>>(q, k, nullptr, p, H_, H_, H_, S_,
                                        (long)S_ * H_, (long)S_ * H_, (long)S_ * S_,
                                        0.03125f);

    // 3) Row softmax (causal prefix)
    softmax_rows<<<M, blk>>>(p);

    // 4) O = P @ V  (B = V^T, NT form, causal k-limit)
    const dim3 gp(H_ / BN, S_ / BM, B_);  // (8, 16, 8)
    gemm_nt<3><<<gp, blk, SMEM_BYTES>>>(p, vt, nullptr, out, S_, S_, B_ * S_, H_,
                                        (long)S_ * S_, (long)S_, (long)S_ * H_, 1.f);
}

// round 6
// speedup vs baseline: 3.3547x; 1.0885x over previous
#include <cuda_runtime.h>
#include <cuda_fp16.h>
#include <cstdint>
#include <math.h>

static constexpr int B_ = 8, S_ = 2048, D_ = 1024, H_ = 1024;
static constexpr int M_ = B_ * S_;  // 16384

// Tiling: 128x128 CTA tile, BK=32. fp16 planes in SMEM: A_h, B_h, B_l.
static constexpr int BM = 128, BN = 128, BK = 32;
static constexpr int ROWB = 80;                    // 64 data bytes + 16 pad
static constexpr int PL = BM * ROWB;               // 10240 per plane
static constexpr int STG = 3 * PL;                 // 30720 per stage
static constexpr int NST = 3;
static constexpr int SMEM_BYTES = NST * STG;       // 92160

// Device scratch (allocation-free rule: __device__ globals)
__device__ __half g_xh[(size_t)M_ * D_];
__device__ __half g_wh[3][(size_t)H_ * D_];
__device__ __half g_wl[3][(size_t)H_ * D_];
__device__ __half g_qh[(size_t)M_ * H_];
__device__ __half g_kh[(size_t)M_ * H_];
__device__ __half g_kl[(size_t)M_ * H_];
__device__ __half g_vh[(size_t)M_ * H_];
__device__ __half g_vl[(size_t)M_ * H_];
__device__ __half g_vth[(size_t)M_ * H_];
__device__ __half g_vtl[(size_t)M_ * H_];
__device__ float  g_p [(size_t)B_ * S_ * S_];
__device__ __half g_ph[(size_t)B_ * S_ * S_];

// ---------------------------------------------------------------------------
// helpers
// ---------------------------------------------------------------------------
__device__ __forceinline__ uint32_t smem_u32(const void* p) {
    uint32_t a;
    asm("{ .reg .u64 t; cvta.to.shared.u64 t, %1; cvt.u32.u64 %0, t; }"
        : "=r"(a) : "l"(p));
    return a;
}

#define CP16(dst, src) \
    asm volatile("cp.async.cg.shared.global [%0], [%1], 16;" :: "r"(dst), "l"(src))
#define CP_COMMIT() asm volatile("cp.async.commit_group;" ::: "memory")
#define CP_WAIT1()  asm volatile("cp.async.wait_group 1;" ::: "memory")

__device__ __forceinline__ void mma16(float* d, const uint32_t* a, const uint32_t* b) {
    asm volatile(
        "mma.sync.aligned.m16n8k16.row.col.f32.f16.f16.f32 "
        "{%0,%1,%2,%3},{%4,%5,%6,%7},{%8,%9},{%0,%1,%2,%3};"
        : "+f"(d[0]), "+f"(d[1]), "+f"(d[2]), "+f"(d[3])
        : "r"(a[0]), "r"(a[1]), "r"(a[2]), "r"(a[3]), "r"(b[0]), "r"(b[1]));
}

__device__ __forceinline__ void ldsm4(uint32_t* r, uint32_t addr) {
    asm volatile(
        "ldmatrix.sync.aligned.m8n8.x4.shared.b16 {%0,%1,%2,%3}, [%4];"
        : "=r"(r[0]), "=r"(r[1]), "=r"(r[2]), "=r"(r[3]) : "r"(addr));
}

// ---------------------------------------------------------------------------
// Per-stage compute: 2 k16 steps, warp tile 64x32, fp16x2 via ldmatrix.
// ---------------------------------------------------------------------------
__device__ __forceinline__ void compute_tile(
    uint32_t buf, float (&acc)[4][4][4], uint32_t aBase, uint32_t bBase)
{
#pragma unroll
    for (int ks = 0; ks < 2; ks++) {
        const uint32_t kb = ks * 32;
        uint32_t bh[2][4], bl[2][4];
#pragma unroll
        for (int ntp = 0; ntp < 2; ntp++) {
            const uint32_t ba = buf + PL + bBase + ntp * 16 * ROWB + kb;
            ldsm4(bh[ntp], ba);
            ldsm4(bl[ntp], ba + PL);
        }
#pragma unroll
        for (int mt = 0; mt < 4; mt++) {
            uint32_t af[4];
            ldsm4(af, buf + aBase + mt * 16 * ROWB + kb);
#pragma unroll
            for (int nt = 0; nt < 4; nt++) {
                const int ntp = nt >> 1, s = nt & 1;
                uint32_t b0[2] = {bh[ntp][s], bh[ntp][s + 2]};
                uint32_t b1[2] = {bl[ntp][s], bl[ntp][s + 2]};
                mma16(acc[mt][nt], af, b0);  // a_hi * b_hi
                mma16(acc[mt][nt], af, b1);  // a_hi * b_lo
            }
        }
    }
}

// ---------------------------------------------------------------------------
// NT GEMM on pre-split fp16 planes: C[m,n] = sum_k A[m,k]*B[n,k]
// MODE 0: Q epilogue   -> half plane + bias
// MODE 1: KV epilogue  -> half hi+lo planes + bias
// MODE 2: scores       -> fp32, scale + causal mask (skip masked tiles)
// MODE 3: PV/out       -> fp32 plain, Kend = m0+BM
// ---------------------------------------------------------------------------
template <int MODE>
__global__ __launch_bounds__(256, 2) void gemm_h(
    const __half* __restrict__ A, const __half* __restrict__ Bh,
    const __half* __restrict__ Bl, const float* __restrict__ bias,
    void* __restrict__ C0, void* __restrict__ C1,
    int K, int lda, int ldb, int ldc,
    long sAz, long sBz, long sCz, float scale)
{
    const int m0 = blockIdx.y * BM;
    const int n0 = blockIdx.x * BN;
    if (MODE == 2 && n0 > m0) return;  // fully masked tile

    const int z = blockIdx.z;
    A  += (size_t)z * sAz;
    Bh += (size_t)z * sBz;
    Bl += (size_t)z * sBz;

    extern __shared__ char smx[];
    const uint32_t smb = smem_u32(smx);

    const int tid  = threadIdx.x;
    const int lane = tid & 31;
    const int wid  = tid >> 5;
    const int wm   = wid >> 2;   // 0..1 (64 rows)
    const int wn   = wid & 3;    // 0..3 (32 cols)
    const int g    = lane >> 2;
    const int tg   = lane & 3;

    // ldmatrix lane addressing
    const uint32_t lq = lane & 15, lh = lane >> 4;
    const uint32_t aBase = (wm * 64 + lq) * ROWB + lh * 16;
    const uint32_t bBase = (wn * 32 + lq) * ROWB + lh * 16;

    const int Kend = (MODE == 3) ? (m0 + BM) : K;
    const int KT   = Kend / BK;

    // cp.async mapping: rows lr4 and lr4+64, 16B segment c of the 64B row
    const int lr4 = tid >> 2;
    const int c16 = tid & 3;
    const __half* pA  = A  + (size_t)(m0 + lr4) * lda + c16 * 8;
    const __half* pBh = Bh + (size_t)(n0 + lr4) * ldb + c16 * 8;
    const __half* pBl = Bl + (size_t)(n0 + lr4) * ldb + c16 * 8;
    const size_t a64 = (size_t)64 * lda, b64 = (size_t)64 * ldb;
    const uint32_t dst0 = smb + lr4 * ROWB + c16 * 16;

    float acc[4][4][4];
#pragma unroll
    for (int i = 0; i < 4; i++)
#pragma unroll
        for (int j = 0; j < 4; j++)
#pragma unroll
            for (int e = 0; e < 4; e++) acc[i][j][e] = 0.f;

#define ISSUE(kt)                                                          \
    do {                                                                   \
        const uint32_t d = dst0 + ((kt) % NST) * STG;                      \
        const int koff = (kt) * BK;                                        \
        CP16(d,                  pA  + koff);                              \
        CP16(d + 64 * ROWB,      pA  + koff + a64);                        \
        CP16(d + PL,             pBh + koff);                              \
        CP16(d + PL + 64 * ROWB, pBh + koff + b64);                        \
        CP16(d + 2 * PL,             pBl + koff);                          \
        CP16(d + 2 * PL + 64 * ROWB, pBl + koff + b64);                    \
        CP_COMMIT();                                                       \
    } while (0)

    ISSUE(0);
    ISSUE(1);

    for (int kt = 0; kt < KT; kt++) {
        CP_WAIT1();          // stage kt resident
        __syncthreads();     // all warps done with buffer being rewritten
        if (kt + 2 < KT) ISSUE(kt + 2);
        compute_tile(smb + (kt % NST) * STG, acc, aBase, bBase);
    }
#undef ISSUE

    // epilogue
#pragma unroll
    for (int mt = 0; mt < 4; mt++)
#pragma unroll
        for (int nt = 0; nt < 4; nt++) {
            const int row = m0 + wm * 64 + mt * 16 + g;
            const int col = n0 + wn * 32 + nt * 8 + tg * 2;
            float* c = acc[mt][nt];
            if (MODE == 0) {
                __half* Ch = (__half*)C0;
                const float2 b2 = *(const float2*)(bias + col);
                __half2 h0 = __floats2half2_rn(c[0] + b2.x, c[1] + b2.y);
                __half2 h1 = __floats2half2_rn(c[2] + b2.x, c[3] + b2.y);
                *(__half2*)(Ch + (size_t)row * ldc + col)       = h0;
                *(__half2*)(Ch + (size_t)(row + 8) * ldc + col) = h1;
            } else if (MODE == 1) {
                __half* Ch = (__half*)C0;
                __half* Cl = (__half*)C1;
                const float2 b2 = *(const float2*)(bias + col);
                const float v0 = c[0] + b2.x, v1 = c[1] + b2.y;
                const float v2 = c[2] + b2.x, v3 = c[3] + b2.y;
                __half2 h0 = __floats2half2_rn(v0, v1);
                __half2 h1 = __floats2half2_rn(v2, v3);
                __half2 l0 = __floats2half2_rn(v0 - __half2float(__low2half(h0)),
                                               v1 - __half2float(__high2half(h0)));
                __half2 l1 = __floats2half2_rn(v2 - __half2float(__low2half(h1)),
                                               v3 - __half2float(__high2half(h1)));
                *(__half2*)(Ch + (size_t)row * ldc + col)       = h0;
                *(__half2*)(Ch + (size_t)(row + 8) * ldc + col) = h1;
                *(__half2*)(Cl + (size_t)row * ldc + col)       = l0;
                *(__half2*)(Cl + (size_t)(row + 8) * ldc + col) = l1;
            } else if (MODE == 2) {
                float* C = (float*)C0 + (size_t)z * sCz;
                float2 v0, v1;
                v0.x = (col     <= row    ) ? c[0] * scale : -1e9f;
                v0.y = (col + 1 <= row    ) ? c[1] * scale : -1e9f;
                v1.x = (col     <= row + 8) ? c[2] * scale : -1e9f;
                v1.y = (col + 1 <= row + 8) ? c[3] * scale : -1e9f;
                *(float2*)(C + (size_t)row * ldc + col)       = v0;
                *(float2*)(C + (size_t)(row + 8) * ldc + col) = v1;
            } else {
                float* C = (float*)C0 + (size_t)z * sCz;
                *(float2*)(C + (size_t)row * ldc + col)       = make_float2(c[0], c[1]);
                *(float2*)(C + (size_t)(row + 8) * ldc + col) = make_float2(c[2], c[3]);
            }
        }
}

// ---------------------------------------------------------------------------
// Conversion kernels (fp32 -> fp16 planes)
// ---------------------------------------------------------------------------
__global__ __launch_bounds__(256) void cvt_h(
    const float* __restrict__ in, __half* __restrict__ out)
{
    const size_t i = ((size_t)blockIdx.x * 256 + threadIdx.x) * 4;
    float4 v = *(const float4*)(in + i);
    __half2 a = __floats2half2_rn(v.x, v.y);
    __half2 b = __floats2half2_rn(v.z, v.w);
    *(__half2*)(out + i)     = a;
    *(__half2*)(out + i + 2) = b;
}

__global__ __launch_bounds__(256) void cvt_hl(
    const float* __restrict__ in, __half* __restrict__ oh, __half* __restrict__ ol)
{
    const size_t i = ((size_t)blockIdx.x * 256 + threadIdx.x) * 4;
    float4 v = *(const float4*)(in + i);
    __half2 h0 = __floats2half2_rn(v.x, v.y);
    __half2 h1 = __floats2half2_rn(v.z, v.w);
    __half2 l0 = __floats2half2_rn(v.x - __half2float(__low2half(h0)),
                                   v.y - __half2float(__high2half(h0)));
    __half2 l1 = __floats2half2_rn(v.z - __half2float(__low2half(h1)),
                                   v.w - __half2float(__high2half(h1)));
    *(__half2*)(oh + i)     = h0;
    *(__half2*)(oh + i + 2) = h1;
    *(__half2*)(ol + i)     = l0;
    *(__half2*)(ol + i + 2) = l1;
}

// ---------------------------------------------------------------------------
// fp16 transpose: in [M_][H_] -> out [H_][M_]
// ---------------------------------------------------------------------------
__global__ __launch_bounds__(256) void transpose_h(
    const __half* __restrict__ in, __half* __restrict__ out)
{
    __shared__ __half t[32][34];
    const int x0 = blockIdx.x * 32;
    const int y0 = blockIdx.y * 32;
    const int tx = threadIdx.x & 31;
    const int ty = threadIdx.x >> 5;
#pragma unroll
    for (int j = 0; j < 32; j += 8)
        t[ty + j][tx] = in[(size_t)(y0 + ty + j) * H_ + x0 + tx];
    __syncthreads();
#pragma unroll
    for (int j = 0; j < 32; j += 8)
        out[(size_t)(x0 + ty + j) * M_ + y0 + tx] = t[tx][ty + j];
}

// ---------------------------------------------------------------------------
// Row softmax: read fp32 scores, write fp16 probabilities (causal prefix).
// ---------------------------------------------------------------------------
__global__ __launch_bounds__(256) void softmax_rows(
    const float* __restrict__ P, __half* __restrict__ Ph)
{
    const int r = blockIdx.x;
    const int m = r & (S_ - 1);
    const float* row = P + (size_t)r * S_;
    __half* orow = Ph + (size_t)r * S_;
    const int KB = ((m >> 7) + 1) << 7;

    __shared__ float buf[S_];
    __shared__ float red[8];
    const int tid = threadIdx.x;

    float mx = -3.4e38f;
    for (int i = tid; i < KB; i += 256) {
        float v = row[i];
        buf[i] = v;
        mx = fmaxf(mx, v);
    }
#pragma unroll
    for (int o = 16; o; o >>= 1) mx = fmaxf(mx, __shfl_xor_sync(0xffffffffu, mx, o));
    if ((tid & 31) == 0) red[tid >> 5] = mx;
    __syncthreads();
    if (tid == 0) {
        float t = red[0];
#pragma unroll
        for (int i = 1; i < 8; i++) t = fmaxf(t, red[i]);
        red[0] = t;
    }
    __syncthreads();
    mx = red[0];
    __syncthreads();

    float sm = 0.f;
    for (int i = tid; i < KB; i += 256) {
        float e = expf(buf[i] - mx);
        buf[i] = e;
        sm += e;
    }
#pragma unroll
    for (int o = 16; o; o >>= 1) sm += __shfl_xor_sync(0xffffffffu, sm, o);
    __syncthreads();
    if ((tid & 31) == 0) red[tid >> 5] = sm;
    __syncthreads();
    if (tid == 0) {
        float t = 0.f;
#pragma unroll
        for (int i = 0; i < 8; i++) t += red[i];
        red[0] = t;
    }
    __syncthreads();
    const float inv = 1.f / red[0];

    for (int i = tid; i < KB; i += 256)
        orow[i] = __float2half_rn(buf[i] * inv);
}

// ---------------------------------------------------------------------------
// Launch pipeline (graph-capturable)
// ---------------------------------------------------------------------------
extern "C" void kernel_launch(void* const* d_in, const int* in_sizes, int n_in,
                              void* d_out, int out_size)
{
    (void)in_sizes; (void)n_in; (void)out_size;
    const float* x  = (const float*)d_in[0];
    const float* Wq = (const float*)d_in[1];
    const float* bq = (const float*)d_in[2];
    const float* Wk = (const float*)d_in[3];
    const float* bk = (const float*)d_in[4];
    const float* Wv = (const float*)d_in[5];
    const float* bv = (const float*)d_in[6];
    float* out = (float*)d_out;

    __half *xh, *qh, *kh, *kl, *vh, *vl, *vth, *vtl, *ph;
    __half (*wh)[(size_t)H_ * D_];
    __half (*wl)[(size_t)H_ * D_];
    float* p;
    cudaGetSymbolAddress((void**)&xh,  g_xh);
    cudaGetSymbolAddress((void**)&wh,  g_wh);
    cudaGetSymbolAddress((void**)&wl,  g_wl);
    cudaGetSymbolAddress((void**)&qh,  g_qh);
    cudaGetSymbolAddress((void**)&kh,  g_kh);
    cudaGetSymbolAddress((void**)&kl,  g_kl);
    cudaGetSymbolAddress((void**)&vh,  g_vh);
    cudaGetSymbolAddress((void**)&vl,  g_vl);
    cudaGetSymbolAddress((void**)&vth, g_vth);
    cudaGetSymbolAddress((void**)&vtl, g_vtl);
    cudaGetSymbolAddress((void**)&p,   g_p);
    cudaGetSymbolAddress((void**)&ph,  g_ph);

    cudaFuncSetAttribute(gemm_h<0>, cudaFuncAttributeMaxDynamicSharedMemorySize, SMEM_BYTES);
    cudaFuncSetAttribute(gemm_h<1>, cudaFuncAttributeMaxDynamicSharedMemorySize, SMEM_BYTES);
    cudaFuncSetAttribute(gemm_h<2>, cudaFuncAttributeMaxDynamicSharedMemorySize, SMEM_BYTES);
    cudaFuncSetAttribute(gemm_h<3>, cudaFuncAttributeMaxDynamicSharedMemorySize, SMEM_BYTES);

    const dim3 blk(256);

    // 0) pre-split operands to fp16 planes
    cvt_h <<<M_ * D_ / 1024, blk>>>(x, xh);
    cvt_hl<<<H_ * D_ / 1024, blk>>>(Wq, wh[0], wl[0]);
    cvt_hl<<<H_ * D_ / 1024, blk>>>(Wk, wh[1], wl[1]);
    cvt_hl<<<H_ * D_ / 1024, blk>>>(Wv, wh[2], wl[2]);

    // 1) QKV projections (A = xh; B = W hi/lo)
    const dim3 gq(H_ / BN, M_ / BM, 1);
    gemm_h<0><<<gq, blk, SMEM_BYTES>>>(xh, wh[0], wl[0], bq, qh, nullptr,
                                       D_, D_, D_, H_, 0, 0, 0, 1.f);
    gemm_h<1><<<gq, blk, SMEM_BYTES>>>(xh, wh[1], wl[1], bk, kh, kl,
                                       D_, D_, D_, H_, 0, 0, 0, 1.f);
    gemm_h<1><<<gq, blk, SMEM_BYTES>>>(xh, wh[2], wl[2], bv, vh, vl,
                                       D_, D_, D_, H_, 0, 0, 0, 1.f);

    // 1b) V^T planes for the PV GEMM
    const dim3 gt(H_ / 32, M_ / 32);
    transpose_h<<<gt, blk>>>(vh, vth);
    transpose_h<<<gt, blk>>>(vl, vtl);

    // 2) Scores: per batch, Q @ K^T / 32, causal
    const dim3 gs(S_ / BN, S_ / BM, B_);
    gemm_h<2><<<gs, blk, SMEM_BYTES>>>(qh, kh, kl, nullptr, p, nullptr,
                                       H_, H_, H_, S_,
                                       (long)S_ * H_, (long)S_ * H_, (long)S_ * S_,
                                       0.03125f);

    // 3) Row softmax -> fp16 P
    softmax_rows<<<M_, blk>>>(p, ph);

    // 4) O = P @ V (B = V^T hi/lo planes, causal k-limit)
    const dim3 gp(H_ / BN, S_ / BM, B_);
    gemm_h<3><<<gp, blk, SMEM_BYTES>>>(ph, vth, vtl, nullptr, out, nullptr,
                                       S_, S_, M_, H_,
                                       (long)S_ * S_, (long)S_, (long)S_ * H_, 1.f);
}